// round 2
// baseline (speedup 1.0000x reference)
#include <cuda_runtime.h>
#include <math.h>

#define TGT 512
#define BSZ 16
#define EDIM 1024
#define NH 16
#define HD 64
#define NS 32
#define BH 256          // bsz*H
#define MROWS 8192      // tgt*bsz

// ---------------- scratch (device globals: no allocation allowed) ----------
__device__ float g_v[(size_t)BH * TGT * HD];         // V projected, (bh, t, d)  32 MB
__device__ float g_attn[(size_t)BH * TGT * TGT];     // softmax probs           268 MB
__device__ float g_ao[(size_t)MROWS * EDIM];         // attn out pre-proj       32 MB
__device__ int   g_mask_flag;                        // 0=f32, 1=i32, 2=bytes

// ---------------- mask dtype detection ------------------------------------
__global__ void detect_mask_kernel(const unsigned int* __restrict__ m) {
    __shared__ int sf, sb;
    if (threadIdx.x == 0) { sf = 0; sb = 0; }
    __syncthreads();
    int f = 0, bt = 0;
    for (int i = threadIdx.x; i < 4096; i += blockDim.x) {
        unsigned w = m[i];
        if (w == 0x3F800000u) f = 1;
        else if (w & 0xFFFFFF00u) bt = 1;
    }
    if (f)  atomicOr(&sf, 1);
    if (bt) atomicOr(&sb, 1);
    __syncthreads();
    if (threadIdx.x == 0) g_mask_flag = sf ? 0 : (sb ? 2 : 1);
}

// ---------------- fused aw-projection + mask + softmax + avg ---------------
// one block per (b, n). adj row (32 x 512) staged in smem, logits for all 16
// heads computed in smem, rowwise softmax, probs -> g_attn, avg -> d_out tail.
__global__ void __launch_bounds__(256) attn_kernel(
    const float* __restrict__ adj, const void* __restrict__ maskp,
    const float* __restrict__ posw, const float* __restrict__ posb,
    float* __restrict__ avg_out)
{
    extern __shared__ float sh[];
    float* s_adj  = sh;                   // 32*512 = 16384
    float* s_log  = sh + 16384;           // 16*512 = 8192
    float* s_mask = s_log + 8192;         // 512
    float* s_pw   = s_mask + 512;         // 32*16 (transposed: [s][h])
    float* s_red  = s_pw + 512;           // 32

    const int tid = threadIdx.x;
    const int b = blockIdx.x >> 9;
    const int n = blockIdx.x & 511;

    // stage adj[b, :, n, :]  (32 rows of 512 contiguous floats)
    for (int i = tid; i < NS * TGT / 4; i += 256) {
        int s = i >> 7;
        int mc = i & 127;
        float4 v = *(const float4*)(adj + ((size_t)(b * NS + s) * TGT + n) * TGT + mc * 4);
        *(float4*)(s_adj + s * TGT + mc * 4) = v;
    }
    // mask row -> additive
    const int flag = g_mask_flag;
    const size_t moff = ((size_t)b * TGT + n) * TGT;
    for (int m = tid; m < TGT; m += 256) {
        bool on;
        if (flag == 0)      on = ((const float*)maskp)[moff + m] != 0.0f;
        else if (flag == 1) on = ((const int*)maskp)[moff + m] != 0;
        else                on = ((const unsigned char*)maskp)[moff + m] != 0;
        s_mask[m] = on ? -1000000.0f : 0.0f;
    }
    // pos_weight transposed for vectorized h-loads
    for (int i = tid; i < NH * NS; i += 256) {
        int h = i >> 5, s = i & 31;
        s_pw[s * NH + h] = posw[i];
    }
    __syncthreads();

    // logits: thread -> 4 heads x 4 m's microtile
    {
        const int hq = tid >> 6;        // 0..3
        const int mt = tid & 63;        // 0..63
        const int h0 = hq * 4;
        for (int p = 0; p < 2; p++) {
            const int m0 = p * 256 + mt * 4;
            float acc[4][4] = {};
            #pragma unroll
            for (int s = 0; s < NS; s++) {
                float4 av = *(float4*)(s_adj + s * TGT + m0);
                float4 pv = *(float4*)(s_pw + s * NH + h0);
                float a4[4] = {av.x, av.y, av.z, av.w};
                float p4[4] = {pv.x, pv.y, pv.z, pv.w};
                #pragma unroll
                for (int i = 0; i < 4; i++)
                    #pragma unroll
                    for (int j = 0; j < 4; j++)
                        acc[i][j] += p4[i] * a4[j];
            }
            #pragma unroll
            for (int i = 0; i < 4; i++)
                #pragma unroll
                for (int j = 0; j < 4; j++)
                    s_log[(h0 + i) * TGT + m0 + j] = acc[i][j];
        }
    }
    __syncthreads();

    // rowwise softmax per head; accumulate average over heads in regs
    const int lane = tid & 31, wid = tid >> 5;
    float avg0 = 0.0f, avg1 = 0.0f;
    const size_t base_bh = (size_t)(b * NH) * TGT * TGT + (size_t)n * TGT;
    for (int h = 0; h < NH; h++) {
        const float pb = posb[h];
        float l0 = s_log[h * TGT + tid] + pb + s_mask[tid];
        float l1 = s_log[h * TGT + 256 + tid] + pb + s_mask[256 + tid];
        float mx = fmaxf(l0, l1);
        #pragma unroll
        for (int o = 16; o; o >>= 1) mx = fmaxf(mx, __shfl_xor_sync(0xFFFFFFFFu, mx, o));
        if (lane == 0) s_red[wid] = mx;
        __syncthreads();
        if (wid == 0) {
            float v = s_red[lane & 7];
            #pragma unroll
            for (int o = 4; o; o >>= 1) v = fmaxf(v, __shfl_xor_sync(0xFFFFFFFFu, v, o));
            if (lane == 0) s_red[0] = v;
        }
        __syncthreads();
        mx = s_red[0];
        float e0 = __expf(l0 - mx), e1 = __expf(l1 - mx);
        float sm = e0 + e1;
        #pragma unroll
        for (int o = 16; o; o >>= 1) sm += __shfl_xor_sync(0xFFFFFFFFu, sm, o);
        __syncthreads();   // s_red[0] consumed by all before overwrite
        if (lane == 0) s_red[wid] = sm;
        __syncthreads();
        if (wid == 0) {
            float v = s_red[lane & 7];
            #pragma unroll
            for (int o = 4; o; o >>= 1) v += __shfl_xor_sync(0xFFFFFFFFu, v, o);
            if (lane == 0) s_red[0] = v;
        }
        __syncthreads();
        const float inv = 1.0f / s_red[0];
        const float p0 = e0 * inv, p1 = e1 * inv;
        avg0 += p0; avg1 += p1;
        float* dst = g_attn + base_bh + (size_t)h * TGT * TGT;
        dst[tid] = p0;
        dst[256 + tid] = p1;
        __syncthreads();   // protect s_red for next head
    }
    float* av = avg_out + ((size_t)b * TGT + n) * TGT;
    av[tid]       = avg0 * (1.0f / NH);
    av[256 + tid] = avg1 * (1.0f / NH);
}

// ---------------- big NT SGEMM: C[m,n] = sum_k A[m,k]*B[n,k] + bias[n] -----
// M=8192, N=1024, K=1024. MODE 0: A=value, scatter C into g_v (bh,t,d) layout.
// MODE 1: A=g_ao, C=d_out rows (t,b) x cols E.
template <int MODE>
__global__ void __launch_bounds__(256) gemm_nt_kernel(
    const float* __restrict__ Ain, const float* __restrict__ B,
    const float* __restrict__ bias, float* __restrict__ C)
{
    __shared__ float As[16][132];
    __shared__ float Bs[16][132];
    const float* A = (MODE == 0) ? Ain : g_ao;

    const int tid = threadIdx.x;
    const int m0 = blockIdx.y * 128;
    const int n0 = blockIdx.x * 128;
    const int ty = tid >> 4, tx = tid & 15;

    float acc[8][8] = {};
    float ra[8], rb[8];

    for (int k0 = 0; k0 < 1024; k0 += 16) {
        #pragma unroll
        for (int q = 0; q < 2; q++) {
            int f = tid + q * 256;
            int m = f >> 2, kc = f & 3;
            float4 va = *(const float4*)(A + (size_t)(m0 + m) * 1024 + k0 + kc * 4);
            As[kc * 4 + 0][m] = va.x; As[kc * 4 + 1][m] = va.y;
            As[kc * 4 + 2][m] = va.z; As[kc * 4 + 3][m] = va.w;
            float4 vb = *(const float4*)(B + (size_t)(n0 + m) * 1024 + k0 + kc * 4);
            Bs[kc * 4 + 0][m] = vb.x; Bs[kc * 4 + 1][m] = vb.y;
            Bs[kc * 4 + 2][m] = vb.z; Bs[kc * 4 + 3][m] = vb.w;
        }
        __syncthreads();
        #pragma unroll
        for (int kk = 0; kk < 16; kk++) {
            *(float4*)&ra[0] = *(float4*)&As[kk][ty * 4];
            *(float4*)&ra[4] = *(float4*)&As[kk][ty * 4 + 64];
            *(float4*)&rb[0] = *(float4*)&Bs[kk][tx * 4];
            *(float4*)&rb[4] = *(float4*)&Bs[kk][tx * 4 + 64];
            #pragma unroll
            for (int i = 0; i < 8; i++)
                #pragma unroll
                for (int j = 0; j < 8; j++)
                    acc[i][j] += ra[i] * rb[j];
        }
        __syncthreads();
    }

    #pragma unroll
    for (int i = 0; i < 8; i++) {
        int mi = m0 + ty * 4 + ((i < 4) ? i : 64 + i - 4);
        #pragma unroll
        for (int j = 0; j < 8; j++) {
            int nj = n0 + tx * 4 + ((j < 4) ? j : 64 + j - 4);
            float v = acc[i][j] + bias[nj];
            if (MODE == 0) {
                int t = mi >> 4, bb = mi & 15;     // value rows: r = t*16 + b
                int h = nj >> 6, d = nj & 63;
                g_v[(((size_t)(bb * 16 + h)) * TGT + t) * HD + d] = v;
            } else {
                C[(size_t)mi * 1024 + nj] = v;
            }
        }
    }
}

// ---------------- attn @ V : per-bh (512x64) = (512x512)(512x64) -----------
__global__ void __launch_bounds__(256) av_kernel() {
    const int bh  = blockIdx.x >> 3;
    const int tt0 = (blockIdx.x & 7) * 64;
    const int b = bh >> 4, h = bh & 15;

    __shared__ float Ps[32][68];
    __shared__ float Vs[32][68];

    const float* P = g_attn + (size_t)bh * TGT * TGT;
    const float* V = g_v + (size_t)bh * TGT * HD;

    const int tid = threadIdx.x;
    const int tr = tid >> 4, dcv = tid & 15;
    float acc[4][4] = {};

    for (int k0 = 0; k0 < 512; k0 += 32) {
        #pragma unroll
        for (int q = 0; q < 2; q++) {
            int f = tid + q * 256;
            int t = f >> 3, kc = f & 7;
            float4 v = *(const float4*)(P + (size_t)(tt0 + t) * 512 + k0 + kc * 4);
            Ps[kc * 4 + 0][t] = v.x; Ps[kc * 4 + 1][t] = v.y;
            Ps[kc * 4 + 2][t] = v.z; Ps[kc * 4 + 3][t] = v.w;
        }
        #pragma unroll
        for (int q = 0; q < 2; q++) {
            int f = tid + q * 256;
            int k = f >> 4, dc = f & 15;
            *(float4*)&Vs[k][dc * 4] = *(const float4*)(V + (size_t)(k0 + k) * 64 + dc * 4);
        }
        __syncthreads();
        #pragma unroll
        for (int kk = 0; kk < 32; kk++) {
            float4 a = *(float4*)&Ps[kk][tr * 4];
            float4 bv = *(float4*)&Vs[kk][dcv * 4];
            float a4[4] = {a.x, a.y, a.z, a.w};
            float b4[4] = {bv.x, bv.y, bv.z, bv.w};
            #pragma unroll
            for (int i = 0; i < 4; i++)
                #pragma unroll
                for (int j = 0; j < 4; j++)
                    acc[i][j] += a4[i] * b4[j];
        }
        __syncthreads();
    }

    #pragma unroll
    for (int i = 0; i < 4; i++) {
        int t = tt0 + tr * 4 + i;
        #pragma unroll
        for (int j = 0; j < 4; j++) {
            int d = dcv * 4 + j;
            g_ao[((size_t)t * BSZ + b) * EDIM + h * HD + d] = acc[i][j];
        }
    }
}

// ---------------- launch ---------------------------------------------------
extern "C" void kernel_launch(void* const* d_in, const int* in_sizes, int n_in,
                              void* d_out, int out_size) {
    (void)in_sizes; (void)n_in; (void)out_size;
    const float* value = (const float*)d_in[0];
    const float* adj   = (const float*)d_in[1];
    const void*  mask  = d_in[2];
    const float* w_in  = (const float*)d_in[3];
    const float* b_in  = (const float*)d_in[4];
    const float* w_out = (const float*)d_in[5];
    const float* b_out = (const float*)d_in[6];
    const float* posw  = (const float*)d_in[7];
    const float* posb  = (const float*)d_in[8];

    float* out = (float*)d_out;
    float* avg = out + (size_t)TGT * BSZ * EDIM;   // outputs concatenated

    detect_mask_kernel<<<1, 256>>>((const unsigned int*)mask);

    dim3 gg(EDIM / 128, MROWS / 128);
    gemm_nt_kernel<0><<<gg, 256>>>(value, w_in, b_in, nullptr);

    constexpr int SMEM2 = (16384 + 8192 + 512 + 512 + 32) * 4;   // ~102.5 KB
    cudaFuncSetAttribute((const void*)attn_kernel,
                         cudaFuncAttributeMaxDynamicSharedMemorySize, SMEM2);
    attn_kernel<<<BSZ * TGT, 256, SMEM2>>>(adj, mask, posw, posb, avg);

    av_kernel<<<BH * 8, 256>>>();

    gemm_nt_kernel<1><<<gg, 256>>>(nullptr, w_out, b_out, out);
}

// round 3
// speedup vs baseline: 2.0035x; 2.0035x over previous
#include <cuda_runtime.h>
#include <math.h>

#define TGT 512
#define BSZ 16
#define EDIM 1024
#define NH 16
#define HD 64
#define NS 32
#define BH 256          // bsz*H
#define MROWS 8192      // tgt*bsz

// ---------------- scratch (device globals: no allocation allowed) ----------
__device__ float g_v[(size_t)BH * TGT * HD];         // V projected, (bh, t, d)  32 MB
__device__ float g_attn[(size_t)BH * TGT * TGT];     // softmax probs           268 MB
__device__ float g_ao[(size_t)MROWS * EDIM];         // attn out pre-proj       32 MB
__device__ int   g_mask_flag;                        // 0=f32, 1=i32, 2=bytes

// ---------------- helpers ---------------------------------------------------
__device__ __forceinline__ unsigned f2tf32(float f) {
    unsigned u;
    asm("cvt.rna.tf32.f32 %0, %1;" : "=r"(u) : "f"(f));
    return u;
}

__device__ __forceinline__ void mma_tf32(float* d, const unsigned* a, const unsigned* b) {
    asm volatile(
        "mma.sync.aligned.m16n8k8.row.col.f32.tf32.tf32.f32 "
        "{%0,%1,%2,%3}, {%4,%5,%6,%7}, {%8,%9}, {%0,%1,%2,%3};"
        : "+f"(d[0]), "+f"(d[1]), "+f"(d[2]), "+f"(d[3])
        : "r"(a[0]), "r"(a[1]), "r"(a[2]), "r"(a[3]), "r"(b[0]), "r"(b[1]));
}

// ---------------- mask dtype detection ------------------------------------
__global__ void detect_mask_kernel(const unsigned int* __restrict__ m) {
    __shared__ int sf, sb;
    if (threadIdx.x == 0) { sf = 0; sb = 0; }
    __syncthreads();
    int f = 0, bt = 0;
    for (int i = threadIdx.x; i < 4096; i += blockDim.x) {
        unsigned w = m[i];
        if (w == 0x3F800000u) f = 1;
        else if (w & 0xFFFFFF00u) bt = 1;
    }
    if (f)  atomicOr(&sf, 1);
    if (bt) atomicOr(&sb, 1);
    __syncthreads();
    if (threadIdx.x == 0) g_mask_flag = sf ? 0 : (sb ? 2 : 1);
}

// ---------------- fused aw-projection + mask + softmax + avg ---------------
// one block per (b, n). warp w owns heads w and w+8 end-to-end (no per-head
// block syncs). probs -> g_attn and back into s_log for the head-average.
__global__ void __launch_bounds__(256) attn_kernel(
    const float* __restrict__ adj, const void* __restrict__ maskp,
    const float* __restrict__ posw, const float* __restrict__ posb,
    float* __restrict__ avg_out)
{
    extern __shared__ float sh[];
    float* s_adj  = sh;                   // 32*512
    float* s_log  = sh + 16384;           // 16*512
    float* s_mask = s_log + 8192;         // 512
    float* s_pw   = s_mask + 512;         // 32*16 transposed [s][h]

    const int tid = threadIdx.x;
    const int b = blockIdx.x >> 9;
    const int n = blockIdx.x & 511;

    // stage adj[b, :, n, :]
    for (int i = tid; i < NS * TGT / 4; i += 256) {
        int s = i >> 7;
        int mc = i & 127;
        float4 v = *(const float4*)(adj + ((size_t)(b * NS + s) * TGT + n) * TGT + mc * 4);
        *(float4*)(s_adj + s * TGT + mc * 4) = v;
    }
    // mask row -> additive
    const int flag = g_mask_flag;
    const size_t moff = ((size_t)b * TGT + n) * TGT;
    for (int m = tid; m < TGT; m += 256) {
        bool on;
        if (flag == 0)      on = ((const float*)maskp)[moff + m] != 0.0f;
        else if (flag == 1) on = ((const int*)maskp)[moff + m] != 0;
        else                on = ((const unsigned char*)maskp)[moff + m] != 0;
        s_mask[m] = on ? -1000000.0f : 0.0f;
    }
    for (int i = tid; i < NH * NS; i += 256) {
        int h = i >> 5, s = i & 31;
        s_pw[s * NH + h] = posw[i];
    }
    __syncthreads();

    // logits: thread -> 4 heads x 4 m's microtile
    {
        const int hq = tid >> 6;
        const int mt = tid & 63;
        const int h0 = hq * 4;
        for (int p = 0; p < 2; p++) {
            const int m0 = p * 256 + mt * 4;
            float acc[4][4] = {};
            #pragma unroll
            for (int s = 0; s < NS; s++) {
                float4 av = *(float4*)(s_adj + s * TGT + m0);
                float4 pv = *(float4*)(s_pw + s * NH + h0);
                float a4[4] = {av.x, av.y, av.z, av.w};
                float p4[4] = {pv.x, pv.y, pv.z, pv.w};
                #pragma unroll
                for (int i = 0; i < 4; i++)
                    #pragma unroll
                    for (int j = 0; j < 4; j++)
                        acc[i][j] += p4[i] * a4[j];
            }
            #pragma unroll
            for (int i = 0; i < 4; i++)
                #pragma unroll
                for (int j = 0; j < 4; j++)
                    s_log[(h0 + i) * TGT + m0 + j] = acc[i][j];
        }
    }
    __syncthreads();

    // per-warp softmax: warp w handles heads w, w+8. whole row in registers.
    const int lane = tid & 31, w = tid >> 5;
    float msk[16];
    #pragma unroll
    for (int j = 0; j < 16; j++) msk[j] = s_mask[j * 32 + lane];

    #pragma unroll
    for (int hh = 0; hh < 2; hh++) {
        const int h = w + hh * 8;
        const float pb = posb[h];
        float l[16];
        float mx = -3.4e38f;
        #pragma unroll
        for (int j = 0; j < 16; j++) {
            l[j] = s_log[h * TGT + j * 32 + lane] + pb + msk[j];
            mx = fmaxf(mx, l[j]);
        }
        #pragma unroll
        for (int o = 16; o; o >>= 1) mx = fmaxf(mx, __shfl_xor_sync(0xFFFFFFFFu, mx, o));
        float sm = 0.0f;
        #pragma unroll
        for (int j = 0; j < 16; j++) { l[j] = __expf(l[j] - mx); sm += l[j]; }
        #pragma unroll
        for (int o = 16; o; o >>= 1) sm += __shfl_xor_sync(0xFFFFFFFFu, sm, o);
        const float inv = 1.0f / sm;
        float* dst = g_attn + ((size_t)(b * NH + h) * TGT + n) * TGT;
        #pragma unroll
        for (int j = 0; j < 16; j++) {
            float p = l[j] * inv;
            dst[j * 32 + lane] = p;
            s_log[h * TGT + j * 32 + lane] = p;   // own head's row only
        }
    }
    __syncthreads();

    // head-average
    float* av = avg_out + ((size_t)b * TGT + n) * TGT;
    #pragma unroll
    for (int q = 0; q < 2; q++) {
        int m = tid + q * 256;
        float s = 0.0f;
        #pragma unroll
        for (int h = 0; h < NH; h++) s += s_log[h * TGT + m];
        av[m] = s * (1.0f / NH);
    }
}

// ---------------- big NT GEMM via TF32 MMA: C[m,n]=A[m,:]·B[n,:]+bias[n] ---
// M=8192, N=1024, K=1024. block tile 128x128, 8 warps of 64x32, K-tile 32.
// MODE 0: A=value, scatter C into g_v (bh,t,d). MODE 1: A=g_ao, C=d_out.
template <int MODE>
__global__ void __launch_bounds__(256) gemm_tc_kernel(
    const float* __restrict__ Ain, const float* __restrict__ B,
    const float* __restrict__ bias, float* __restrict__ C)
{
    __shared__ unsigned As[128][36];   // [m][k], stride 36 -> conflict-free frags
    __shared__ unsigned Bs[128][36];   // [n][k]
    const float* A = (MODE == 0) ? Ain : g_ao;

    const int tid = threadIdx.x;
    const int m_blk = blockIdx.y * 128;
    const int n_blk = blockIdx.x * 128;
    const int warp = tid >> 5, lane = tid & 31;
    const int wm = (warp & 1) * 64, wn = (warp >> 1) * 32;
    const int qr = lane >> 2, qc = lane & 3;

    const int srow = tid >> 3;       // 0..31 (+q*32)
    const int sc4  = tid & 7;        // float4 index along k

    float d[4][4][4];
    #pragma unroll
    for (int i = 0; i < 4; i++)
        #pragma unroll
        for (int j = 0; j < 4; j++)
            #pragma unroll
            for (int r = 0; r < 4; r++) d[i][j][r] = 0.0f;

    float4 fa[4], fb[4];
    #pragma unroll
    for (int q = 0; q < 4; q++) {
        fa[q] = *(const float4*)(A + (size_t)(m_blk + srow + q * 32) * 1024 + sc4 * 4);
        fb[q] = *(const float4*)(B + (size_t)(n_blk + srow + q * 32) * 1024 + sc4 * 4);
    }

    for (int k0 = 0; k0 < 1024; k0 += 32) {
        #pragma unroll
        for (int q = 0; q < 4; q++) {
            uint4 ua = make_uint4(f2tf32(fa[q].x), f2tf32(fa[q].y), f2tf32(fa[q].z), f2tf32(fa[q].w));
            *(uint4*)&As[srow + q * 32][sc4 * 4] = ua;
            uint4 ub = make_uint4(f2tf32(fb[q].x), f2tf32(fb[q].y), f2tf32(fb[q].z), f2tf32(fb[q].w));
            *(uint4*)&Bs[srow + q * 32][sc4 * 4] = ub;
        }
        __syncthreads();

        if (k0 + 32 < 1024) {
            #pragma unroll
            for (int q = 0; q < 4; q++) {
                fa[q] = *(const float4*)(A + (size_t)(m_blk + srow + q * 32) * 1024 + k0 + 32 + sc4 * 4);
                fb[q] = *(const float4*)(B + (size_t)(n_blk + srow + q * 32) * 1024 + k0 + 32 + sc4 * 4);
            }
        }

        #pragma unroll
        for (int kk = 0; kk < 4; kk++) {
            const int kb = kk * 8;
            unsigned a[4][4], bfr[4][2];
            #pragma unroll
            for (int i = 0; i < 4; i++) {
                a[i][0] = As[wm + i * 16 + qr][kb + qc];
                a[i][1] = As[wm + i * 16 + qr + 8][kb + qc];
                a[i][2] = As[wm + i * 16 + qr][kb + qc + 4];
                a[i][3] = As[wm + i * 16 + qr + 8][kb + qc + 4];
            }
            #pragma unroll
            for (int j = 0; j < 4; j++) {
                bfr[j][0] = Bs[wn + j * 8 + qr][kb + qc];
                bfr[j][1] = Bs[wn + j * 8 + qr][kb + qc + 4];
            }
            #pragma unroll
            for (int i = 0; i < 4; i++)
                #pragma unroll
                for (int j = 0; j < 4; j++)
                    mma_tf32(d[i][j], a[i], bfr[j]);
        }
        __syncthreads();
    }

    // epilogue: c0(r,c) c1(r,c+1) c2(r+8,c) c3(r+8,c+1)
    #pragma unroll
    for (int i = 0; i < 4; i++) {
        #pragma unroll
        for (int j = 0; j < 4; j++) {
            const int mb = m_blk + wm + i * 16 + qr;
            const int nb = n_blk + wn + j * 8 + qc * 2;
            #pragma unroll
            for (int r = 0; r < 4; r++) {
                const int mi = mb + ((r >= 2) ? 8 : 0);
                const int nj = nb + (r & 1);
                const float v = d[i][j][r] + bias[nj];
                if (MODE == 0) {
                    const int t = mi >> 4, bb = mi & 15;
                    const int h = nj >> 6, dd = nj & 63;
                    g_v[(((size_t)(bb * 16 + h)) * TGT + t) * HD + dd] = v;
                } else {
                    C[(size_t)mi * 1024 + nj] = v;
                }
            }
        }
    }
}

// ---------------- attn @ V via TF32 MMA ------------------------------------
// per bh: O(512x64) = P(512x512) V(512x64). block tile 256x64, 8 warps 64x32.
__global__ void __launch_bounds__(256) av_tc_kernel() {
    __shared__ unsigned Ps[256][36];   // [t][k]
    __shared__ unsigned Vs[32][72];    // [k][d], stride 72 -> conflict-free frags

    const int bh = blockIdx.x >> 1;
    const int t0 = (blockIdx.x & 1) * 256;
    const int b = bh >> 4, h = bh & 15;

    const float* P = g_attn + (size_t)bh * TGT * TGT;
    const float* V = g_v + (size_t)bh * TGT * HD;

    const int tid = threadIdx.x;
    const int warp = tid >> 5, lane = tid & 31;
    const int wm = (warp & 3) * 64, wn = (warp >> 2) * 32;
    const int qr = lane >> 2, qc = lane & 3;

    const int prow = tid >> 3;   // 0..31 (+q*32), P staging
    const int pc4  = tid & 7;
    const int vk   = tid >> 4;   // 0..15 (+q*16), V staging
    const int vd4  = tid & 15;

    float d[4][4][4];
    #pragma unroll
    for (int i = 0; i < 4; i++)
        #pragma unroll
        for (int j = 0; j < 4; j++)
            #pragma unroll
            for (int r = 0; r < 4; r++) d[i][j][r] = 0.0f;

    for (int k0 = 0; k0 < 512; k0 += 32) {
        #pragma unroll
        for (int q = 0; q < 8; q++) {
            float4 f = *(const float4*)(P + (size_t)(t0 + prow + q * 32) * 512 + k0 + pc4 * 4);
            uint4 u = make_uint4(f2tf32(f.x), f2tf32(f.y), f2tf32(f.z), f2tf32(f.w));
            *(uint4*)&Ps[prow + q * 32][pc4 * 4] = u;
        }
        #pragma unroll
        for (int q = 0; q < 2; q++) {
            float4 f = *(const float4*)(V + (size_t)(k0 + vk + q * 16) * 64 + vd4 * 4);
            uint4 u = make_uint4(f2tf32(f.x), f2tf32(f.y), f2tf32(f.z), f2tf32(f.w));
            *(uint4*)&Vs[vk + q * 16][vd4 * 4] = u;
        }
        __syncthreads();

        #pragma unroll
        for (int kk = 0; kk < 4; kk++) {
            const int kb = kk * 8;
            unsigned a[4][4], bfr[4][2];
            #pragma unroll
            for (int i = 0; i < 4; i++) {
                a[i][0] = Ps[wm + i * 16 + qr][kb + qc];
                a[i][1] = Ps[wm + i * 16 + qr + 8][kb + qc];
                a[i][2] = Ps[wm + i * 16 + qr][kb + qc + 4];
                a[i][3] = Ps[wm + i * 16 + qr + 8][kb + qc + 4];
            }
            #pragma unroll
            for (int j = 0; j < 4; j++) {
                bfr[j][0] = Vs[kb + qc][wn + j * 8 + qr];
                bfr[j][1] = Vs[kb + qc + 4][wn + j * 8 + qr];
            }
            #pragma unroll
            for (int i = 0; i < 4; i++)
                #pragma unroll
                for (int j = 0; j < 4; j++)
                    mma_tf32(d[i][j], a[i], bfr[j]);
        }
        __syncthreads();
    }

    #pragma unroll
    for (int i = 0; i < 4; i++) {
        #pragma unroll
        for (int j = 0; j < 4; j++) {
            const int tb = t0 + wm + i * 16 + qr;
            const int db = wn + j * 8 + qc * 2;
            #pragma unroll
            for (int r = 0; r < 4; r++) {
                const int t = tb + ((r >= 2) ? 8 : 0);
                const int dd = db + (r & 1);
                g_ao[((size_t)t * BSZ + b) * EDIM + h * HD + dd] = d[i][j][r];
            }
        }
    }
}

// ---------------- launch ---------------------------------------------------
extern "C" void kernel_launch(void* const* d_in, const int* in_sizes, int n_in,
                              void* d_out, int out_size) {
    (void)in_sizes; (void)n_in; (void)out_size;
    const float* value = (const float*)d_in[0];
    const float* adj   = (const float*)d_in[1];
    const void*  mask  = d_in[2];
    const float* w_in  = (const float*)d_in[3];
    const float* b_in  = (const float*)d_in[4];
    const float* w_out = (const float*)d_in[5];
    const float* b_out = (const float*)d_in[6];
    const float* posw  = (const float*)d_in[7];
    const float* posb  = (const float*)d_in[8];

    float* out = (float*)d_out;
    float* avg = out + (size_t)TGT * BSZ * EDIM;

    detect_mask_kernel<<<1, 256>>>((const unsigned int*)mask);

    dim3 gg(EDIM / 128, MROWS / 128);
    gemm_tc_kernel<0><<<gg, 256>>>(value, w_in, b_in, nullptr);

    constexpr int SMEM2 = (16384 + 8192 + 512 + 512 + 32) * 4;
    cudaFuncSetAttribute((const void*)attn_kernel,
                         cudaFuncAttributeMaxDynamicSharedMemorySize, SMEM2);
    attn_kernel<<<BSZ * TGT, 256, SMEM2>>>(adj, mask, posw, posb, avg);

    av_tc_kernel<<<BH * 2, 256>>>();

    gemm_tc_kernel<1><<<gg, 256>>>(nullptr, w_out, b_out, out);
}

// round 4
// speedup vs baseline: 3.6567x; 1.8252x over previous
#include <cuda_runtime.h>
#include <math.h>

#define TGT 512
#define BSZ 16
#define EDIM 1024
#define NH 16
#define HD 64
#define NS 32
#define BH 256          // bsz*H
#define MROWS 8192      // tgt*bsz

// ---------------- scratch (device globals: no allocation allowed) ----------
__device__ __align__(16) float g_v[(size_t)BH * TGT * HD];     // V projected (bh,t,d)
__device__ __align__(16) float g_attn[(size_t)BH * TGT * TGT]; // softmax probs
__device__ __align__(16) float g_ao[(size_t)MROWS * EDIM];     // attn out pre-proj (tf32-rounded)
__device__ __align__(16) float g_val[(size_t)MROWS * EDIM];    // value, tf32-rounded
__device__ __align__(16) float g_w0[(size_t)EDIM * EDIM];      // in_proj_weight rounded
__device__ __align__(16) float g_w1[(size_t)EDIM * EDIM];      // out_proj_weight rounded
__device__ int g_mask_flag;                                    // 0=f32, 1=i32, 2=bytes

// ---------------- helpers ---------------------------------------------------
__device__ __forceinline__ unsigned f2tf32(float f) {
    unsigned u;
    asm("cvt.rna.tf32.f32 %0, %1;" : "=r"(u) : "f"(f));
    return u;
}

__device__ __forceinline__ void mma_tf32(float* d, const unsigned* a, const unsigned* b) {
    asm volatile(
        "mma.sync.aligned.m16n8k8.row.col.f32.tf32.tf32.f32 "
        "{%0,%1,%2,%3}, {%4,%5,%6,%7}, {%8,%9}, {%0,%1,%2,%3};"
        : "+f"(d[0]), "+f"(d[1]), "+f"(d[2]), "+f"(d[3])
        : "r"(a[0]), "r"(a[1]), "r"(a[2]), "r"(a[3]), "r"(b[0]), "r"(b[1]));
}

__device__ __forceinline__ void cp_async16(const float* smem_dst, const float* gsrc) {
    unsigned s = (unsigned)__cvta_generic_to_shared(smem_dst);
    asm volatile("cp.async.cg.shared.global [%0], [%1], 16;" :: "r"(s), "l"(gsrc));
}
__device__ __forceinline__ void cp_commit() { asm volatile("cp.async.commit_group;"); }

// ---------------- mask dtype detection ------------------------------------
__global__ void detect_mask_kernel(const unsigned int* __restrict__ m) {
    __shared__ int sf, sb;
    if (threadIdx.x == 0) { sf = 0; sb = 0; }
    __syncthreads();
    int f = 0, bt = 0;
    for (int i = threadIdx.x; i < 4096; i += blockDim.x) {
        unsigned w = m[i];
        if (w == 0x3F800000u) f = 1;
        else if (w & 0xFFFFFF00u) bt = 1;
    }
    if (f)  atomicOr(&sf, 1);
    if (bt) atomicOr(&sb, 1);
    __syncthreads();
    if (threadIdx.x == 0) g_mask_flag = sf ? 0 : (sb ? 2 : 1);
}

// ---------------- tf32 pre-rounding pass -----------------------------------
__global__ void round_tf32_kernel(const float4* __restrict__ src, float4* __restrict__ dst, int n4) {
    int i = blockIdx.x * blockDim.x + threadIdx.x;
    if (i < n4) {
        float4 v = src[i];
        v.x = __uint_as_float(f2tf32(v.x));
        v.y = __uint_as_float(f2tf32(v.y));
        v.z = __uint_as_float(f2tf32(v.z));
        v.w = __uint_as_float(f2tf32(v.w));
        dst[i] = v;
    }
}

// ---------------- fused aw-projection + mask + softmax + avg ---------------
// one block per (b, n). Register-accumulated logits: thread owns m = {tid,
// tid+256}, all 16 heads, via packed f32x2 FMA with {w,w}-paired pos weights.
__global__ void __launch_bounds__(256) attn_kernel(
    const float* __restrict__ adj, const void* __restrict__ maskp,
    const float* __restrict__ posw, const float* __restrict__ posb,
    float* __restrict__ avg_out)
{
    __shared__ float s_log[NH][TGT];                  // 32 KB
    __shared__ float s_mask[TGT];                     // 2 KB
    __shared__ unsigned long long s_pw2[NS][NH];      // 4 KB, {w,w} pairs

    const int tid = threadIdx.x;
    const int b = blockIdx.x >> 9;
    const int n = blockIdx.x & 511;

    // mask row -> additive
    const int flag = g_mask_flag;
    const size_t moff = ((size_t)b * TGT + n) * TGT;
    for (int m = tid; m < TGT; m += 256) {
        bool on;
        if (flag == 0)      on = ((const float*)maskp)[moff + m] != 0.0f;
        else if (flag == 1) on = ((const int*)maskp)[moff + m] != 0;
        else                on = ((const unsigned char*)maskp)[moff + m] != 0;
        s_mask[m] = on ? -1000000.0f : 0.0f;
    }
    // pos weights as packed pairs [s][h]
    for (int i = tid; i < NS * NH; i += 256) {
        int s = i >> 4, h = i & 15;
        float w = posw[h * NS + s];
        unsigned long long p;
        asm("mov.b64 %0, {%1,%2};" : "=l"(p) : "f"(w), "f"(w));
        s_pw2[s][h] = p;
    }
    __syncthreads();

    // logits: acc[h] = packed {l(m0=tid), l(m1=tid+256)}
    unsigned long long acc[NH];
    #pragma unroll
    for (int h = 0; h < NH; h++) acc[h] = 0ULL;

    const float* arow = adj + ((size_t)(b * NS) * TGT + n) * TGT;
    #pragma unroll 4
    for (int s = 0; s < NS; s++) {
        float a0 = __ldcs(arow + (size_t)s * (TGT * TGT) + tid);
        float a1 = __ldcs(arow + (size_t)s * (TGT * TGT) + 256 + tid);
        unsigned long long pa;
        asm("mov.b64 %0, {%1,%2};" : "=l"(pa) : "f"(a0), "f"(a1));
        #pragma unroll
        for (int h = 0; h < NH; h++) {
            unsigned long long w2 = s_pw2[s][h];
            asm("fma.rn.f32x2 %0, %1, %2, %0;" : "+l"(acc[h]) : "l"(pa), "l"(w2));
        }
    }
    #pragma unroll
    for (int h = 0; h < NH; h++) {
        float lo, hi;
        asm("mov.b64 {%0,%1}, %2;" : "=f"(lo), "=f"(hi) : "l"(acc[h]));
        s_log[h][tid] = lo;
        s_log[h][tid + 256] = hi;
    }
    __syncthreads();

    // per-warp softmax: warp w handles heads w, w+8; full row in registers.
    const int lane = tid & 31, w = tid >> 5;
    float msk[16];
    #pragma unroll
    for (int j = 0; j < 16; j++) msk[j] = s_mask[j * 32 + lane];

    #pragma unroll
    for (int hh = 0; hh < 2; hh++) {
        const int h = w + hh * 8;
        const float pb = posb[h];
        float l[16];
        float mx = -3.4e38f;
        #pragma unroll
        for (int j = 0; j < 16; j++) {
            l[j] = s_log[h][j * 32 + lane] + pb + msk[j];
            mx = fmaxf(mx, l[j]);
        }
        #pragma unroll
        for (int o = 16; o; o >>= 1) mx = fmaxf(mx, __shfl_xor_sync(0xFFFFFFFFu, mx, o));
        float sm = 0.0f;
        #pragma unroll
        for (int j = 0; j < 16; j++) { l[j] = __expf(l[j] - mx); sm += l[j]; }
        #pragma unroll
        for (int o = 16; o; o >>= 1) sm += __shfl_xor_sync(0xFFFFFFFFu, sm, o);
        const float inv = 1.0f / sm;
        float* dst = g_attn + ((size_t)(b * NH + h) * TGT + n) * TGT;
        #pragma unroll
        for (int j = 0; j < 16; j++) {
            float p = l[j] * inv;
            dst[j * 32 + lane] = p;
            s_log[h][j * 32 + lane] = p;
        }
    }
    __syncthreads();

    // head-average
    float* av = avg_out + ((size_t)b * TGT + n) * TGT;
    #pragma unroll
    for (int q = 0; q < 2; q++) {
        int m = tid + q * 256;
        float s = 0.0f;
        #pragma unroll
        for (int h = 0; h < NH; h++) s += s_log[h][m];
        av[m] = s * (1.0f / NH);
    }
}

// ---------------- big NT GEMM via TF32 MMA, cp.async double-buffered -------
// C[m,n] = A[m,:]·B[n,:] + bias[n]; M=8192, N=1024, K=1024.
// Inputs are PRE-ROUNDED to tf32-exact f32 -> no cvt in the hot loop.
// MODE 0: A=g_val, scatter C into g_v (bh,t,d). MODE 1: A=g_ao, C=d_out.
template <int MODE>
__global__ void __launch_bounds__(256) gemm_tc_kernel(
    const float* __restrict__ Ain, const float* __restrict__ Bin,
    const float* __restrict__ bias, float* __restrict__ C)
{
    extern __shared__ float dyn[];   // As[2][128][36] then Bs[2][128][36]
    const float* A = (MODE == 0) ? Ain : g_ao;
    const float* B = Bin;

    const int tid = threadIdx.x;
    const int m_blk = blockIdx.y * 128;
    const int n_blk = blockIdx.x * 128;
    const int warp = tid >> 5, lane = tid & 31;
    const int wm = (warp & 1) * 64, wn = (warp >> 1) * 32;
    const int qr = lane >> 2, qc = lane & 3;
    const int srow = tid >> 3;       // 0..31 (+q*32)
    const int sc4  = tid & 7;        // k offset /4

    float d[4][4][4];
    #pragma unroll
    for (int i = 0; i < 4; i++)
        #pragma unroll
        for (int j = 0; j < 4; j++)
            #pragma unroll
            for (int r = 0; r < 4; r++) d[i][j][r] = 0.0f;

    const float* ap = A + (size_t)(m_blk + srow) * 1024 + sc4 * 4;
    const float* bp = B + (size_t)(n_blk + srow) * 1024 + sc4 * 4;

    auto stage = [&](int kt, int buf) {
        float* as = dyn + buf * 4608;
        float* bs = dyn + 9216 + buf * 4608;
        #pragma unroll
        for (int q = 0; q < 4; q++) {
            cp_async16(as + (srow + q * 32) * 36 + sc4 * 4, ap + (size_t)q * 32 * 1024 + kt * 32);
            cp_async16(bs + (srow + q * 32) * 36 + sc4 * 4, bp + (size_t)q * 32 * 1024 + kt * 32);
        }
        cp_commit();
    };

    stage(0, 0);

    for (int kt = 0; kt < 32; kt++) {
        if (kt < 31) {
            stage(kt + 1, (kt + 1) & 1);
            asm volatile("cp.async.wait_group 1;");
        } else {
            asm volatile("cp.async.wait_group 0;");
        }
        __syncthreads();

        const float* as = dyn + (kt & 1) * 4608;
        const float* bs = dyn + 9216 + (kt & 1) * 4608;
        #pragma unroll
        for (int kk = 0; kk < 4; kk++) {
            const int kb = kk * 8;
            unsigned a[4][4], bfr[4][2];
            #pragma unroll
            for (int i = 0; i < 4; i++) {
                a[i][0] = __float_as_uint(as[(wm + i * 16 + qr) * 36 + kb + qc]);
                a[i][1] = __float_as_uint(as[(wm + i * 16 + qr + 8) * 36 + kb + qc]);
                a[i][2] = __float_as_uint(as[(wm + i * 16 + qr) * 36 + kb + qc + 4]);
                a[i][3] = __float_as_uint(as[(wm + i * 16 + qr + 8) * 36 + kb + qc + 4]);
            }
            #pragma unroll
            for (int j = 0; j < 4; j++) {
                bfr[j][0] = __float_as_uint(bs[(wn + j * 8 + qr) * 36 + kb + qc]);
                bfr[j][1] = __float_as_uint(bs[(wn + j * 8 + qr) * 36 + kb + qc + 4]);
            }
            #pragma unroll
            for (int i = 0; i < 4; i++)
                #pragma unroll
                for (int j = 0; j < 4; j++)
                    mma_tf32(d[i][j], a[i], bfr[j]);
        }
        __syncthreads();
    }

    // epilogue: c0(r,c) c1(r,c+1) c2(r+8,c) c3(r+8,c+1)
    #pragma unroll
    for (int i = 0; i < 4; i++) {
        #pragma unroll
        for (int j = 0; j < 4; j++) {
            const int mb = m_blk + wm + i * 16 + qr;
            const int nb = n_blk + wn + j * 8 + qc * 2;
            #pragma unroll
            for (int r = 0; r < 4; r++) {
                const int mi = mb + ((r >= 2) ? 8 : 0);
                const int nj = nb + (r & 1);
                const float v = d[i][j][r] + bias[nj];
                if (MODE == 0) {
                    const int t = mi >> 4, bb = mi & 15;
                    const int h = nj >> 6, dd = nj & 63;
                    g_v[(((size_t)(bb * 16 + h)) * TGT + t) * HD + dd] = v;
                } else {
                    C[(size_t)mi * 1024 + nj] = v;
                }
            }
        }
    }
}

// ---------------- attn @ V via TF32 MMA ------------------------------------
// per bh: O(512x64) = P(512x512) V(512x64). block tile 256x64, 8 warps 64x32.
// epilogue rounds g_ao to tf32-exact so gemm<1> can skip conversion.
__global__ void __launch_bounds__(256) av_tc_kernel() {
    __shared__ unsigned Ps[256][36];
    __shared__ unsigned Vs[32][72];

    const int bh = blockIdx.x >> 1;
    const int t0 = (blockIdx.x & 1) * 256;
    const int b = bh >> 4, h = bh & 15;

    const float* P = g_attn + (size_t)bh * TGT * TGT;
    const float* V = g_v + (size_t)bh * TGT * HD;

    const int tid = threadIdx.x;
    const int warp = tid >> 5, lane = tid & 31;
    const int wm = (warp & 3) * 64, wn = (warp >> 2) * 32;
    const int qr = lane >> 2, qc = lane & 3;

    const int prow = tid >> 3;
    const int pc4  = tid & 7;
    const int vk   = tid >> 4;
    const int vd4  = tid & 15;

    float d[4][4][4];
    #pragma unroll
    for (int i = 0; i < 4; i++)
        #pragma unroll
        for (int j = 0; j < 4; j++)
            #pragma unroll
            for (int r = 0; r < 4; r++) d[i][j][r] = 0.0f;

    for (int k0 = 0; k0 < 512; k0 += 32) {
        #pragma unroll
        for (int q = 0; q < 8; q++) {
            float4 f = *(const float4*)(P + (size_t)(t0 + prow + q * 32) * 512 + k0 + pc4 * 4);
            uint4 u = make_uint4(f2tf32(f.x), f2tf32(f.y), f2tf32(f.z), f2tf32(f.w));
            *(uint4*)&Ps[prow + q * 32][pc4 * 4] = u;
        }
        #pragma unroll
        for (int q = 0; q < 2; q++) {
            float4 f = *(const float4*)(V + (size_t)(k0 + vk + q * 16) * 64 + vd4 * 4);
            uint4 u = make_uint4(f2tf32(f.x), f2tf32(f.y), f2tf32(f.z), f2tf32(f.w));
            *(uint4*)&Vs[vk + q * 16][vd4 * 4] = u;
        }
        __syncthreads();

        #pragma unroll
        for (int kk = 0; kk < 4; kk++) {
            const int kb = kk * 8;
            unsigned a[4][4], bfr[4][2];
            #pragma unroll
            for (int i = 0; i < 4; i++) {
                a[i][0] = Ps[wm + i * 16 + qr][kb + qc];
                a[i][1] = Ps[wm + i * 16 + qr + 8][kb + qc];
                a[i][2] = Ps[wm + i * 16 + qr][kb + qc + 4];
                a[i][3] = Ps[wm + i * 16 + qr + 8][kb + qc + 4];
            }
            #pragma unroll
            for (int j = 0; j < 4; j++) {
                bfr[j][0] = Vs[kb + qc][wn + j * 8 + qr];
                bfr[j][1] = Vs[kb + qc + 4][wn + j * 8 + qr];
            }
            #pragma unroll
            for (int i = 0; i < 4; i++)
                #pragma unroll
                for (int j = 0; j < 4; j++)
                    mma_tf32(d[i][j], a[i], bfr[j]);
        }
        __syncthreads();
    }

    #pragma unroll
    for (int i = 0; i < 4; i++) {
        #pragma unroll
        for (int j = 0; j < 4; j++) {
            const int tb = t0 + wm + i * 16 + qr;
            const int db = wn + j * 8 + qc * 2;
            #pragma unroll
            for (int r = 0; r < 4; r++) {
                const int t = tb + ((r >= 2) ? 8 : 0);
                const int dd = db + (r & 1);
                g_ao[((size_t)t * BSZ + b) * EDIM + h * HD + dd] =
                    __uint_as_float(f2tf32(d[i][j][r]));
            }
        }
    }
}

// ---------------- launch ---------------------------------------------------
extern "C" void kernel_launch(void* const* d_in, const int* in_sizes, int n_in,
                              void* d_out, int out_size) {
    (void)in_sizes; (void)n_in; (void)out_size;
    const float* value = (const float*)d_in[0];
    const float* adj   = (const float*)d_in[1];
    const void*  mask  = d_in[2];
    const float* w_in  = (const float*)d_in[3];
    const float* b_in  = (const float*)d_in[4];
    const float* w_out = (const float*)d_in[5];
    const float* b_out = (const float*)d_in[6];
    const float* posw  = (const float*)d_in[7];
    const float* posb  = (const float*)d_in[8];

    float* out = (float*)d_out;
    float* avg = out + (size_t)TGT * BSZ * EDIM;

    float* d_gval; cudaGetSymbolAddress((void**)&d_gval, g_val);
    float* d_gw0;  cudaGetSymbolAddress((void**)&d_gw0, g_w0);
    float* d_gw1;  cudaGetSymbolAddress((void**)&d_gw1, g_w1);

    detect_mask_kernel<<<1, 256>>>((const unsigned int*)mask);

    // pre-round tf32 inputs
    {
        int n4v = MROWS * EDIM / 4;       // 2,097,152
        int n4w = EDIM * EDIM / 4;        // 262,144
        round_tf32_kernel<<<(n4v + 255) / 256, 256>>>((const float4*)value, (float4*)d_gval, n4v);
        round_tf32_kernel<<<(n4w + 255) / 256, 256>>>((const float4*)w_in,  (float4*)d_gw0, n4w);
        round_tf32_kernel<<<(n4w + 255) / 256, 256>>>((const float4*)w_out, (float4*)d_gw1, n4w);
    }

    constexpr int GSMEM = 4 * 4608 * 4;   // 73,728 B
    cudaFuncSetAttribute((const void*)gemm_tc_kernel<0>,
                         cudaFuncAttributeMaxDynamicSharedMemorySize, GSMEM);
    cudaFuncSetAttribute((const void*)gemm_tc_kernel<1>,
                         cudaFuncAttributeMaxDynamicSharedMemorySize, GSMEM);

    dim3 gg(EDIM / 128, MROWS / 128);
    gemm_tc_kernel<0><<<gg, 256, GSMEM>>>(d_gval, d_gw0, b_in, nullptr);

    attn_kernel<<<BSZ * TGT, 256>>>(adj, mask, posw, posb, avg);

    av_tc_kernel<<<BH * 2, 256>>>();

    gemm_tc_kernel<1><<<gg, 256, GSMEM>>>(nullptr, d_gw1, b_out, out);
}